// round 5
// baseline (speedup 1.0000x reference)
#include <cuda_runtime.h>
#include <mma.h>
#include <math.h>
#include <type_traits>

using namespace nvcuda;

// Problem dims
#define NN 512
#define TT 64
#define CC 64
#define HH 4
#define HD 16
#define MM (NN*TT)      // 32768 rows
#define EPS 1e-5f

// ---------------------------------------------------------------------------
// Scratch
// ---------------------------------------------------------------------------
#define SZ 2097152
#define OFF_QH   0
#define OFF_KH   (1*SZ)
#define OFF_VH   (2*SZ)
#define OFF_ATT  (3*SZ)
#define OFF_X    (4*SZ)
#define OFF_H    (5*SZ)     // size 4*SZ
#define OFF_OUT1 (9*SZ)
#define OFF_T1   (10*SZ)
#define OFF_T2   (11*SZ)
#define OFF_T3   (12*SZ)
#define OFF_OUT2 (13*SZ)
#define OFF_ZA   (14*SZ)
#define OFF_PART (15*SZ)
#define OFF_STAT (15*SZ + 1024)
#define SCRATCH_TOTAL (15*SZ + 1024 + 16)

__device__ __align__(16) float g_scratch[SCRATCH_TOTAL];

// ---------------------------------------------------------------------------
// adj InstanceNorm stats (normalization fused into GCN A-staging)
// ---------------------------------------------------------------------------
__global__ void adj_rowred_kernel(const float* __restrict__ adj, float* __restrict__ part) {
    __shared__ float s1[256], s2[256];
    int r = blockIdx.x, t = threadIdx.x;
    float a = adj[r * 512 + t];
    float b = adj[r * 512 + 256 + t];
    s1[t] = a + b;
    s2[t] = a * a + b * b;
    __syncthreads();
    for (int st = 128; st > 0; st >>= 1) {
        if (t < st) { s1[t] += s1[t + st]; s2[t] += s2[t + st]; }
        __syncthreads();
    }
    if (t == 0) { part[r] = s1[0]; part[512 + r] = s2[0]; }
}

__global__ void adj_final_kernel(const float* __restrict__ part, float* __restrict__ stats) {
    __shared__ float s1[256], s2[256];
    int t = threadIdx.x;
    s1[t] = part[t] + part[t + 256];
    s2[t] = part[512 + t] + part[512 + t + 256];
    __syncthreads();
    for (int st = 128; st > 0; st >>= 1) {
        if (t < st) { s1[t] += s1[t + st]; s2[t] += s2[t + st]; }
        __syncthreads();
    }
    if (t == 0) {
        float mean = s1[0] * (1.0f / 262144.0f);
        float var  = s2[0] * (1.0f / 262144.0f) - mean * mean;
        stats[0] = mean;
        stats[1] = rsqrtf(var + EPS);
    }
}

// ---------------------------------------------------------------------------
// Per-head projections q/k/v -> [T,H,N,HD] (conflict-free smem weights)
// ---------------------------------------------------------------------------
__global__ void proj_kernel(const float* __restrict__ q, const float* __restrict__ k,
                            const float* __restrict__ v,
                            const float* __restrict__ Wq, const float* __restrict__ Wk,
                            const float* __restrict__ Wv,
                            float* __restrict__ qh, float* __restrict__ kh,
                            float* __restrict__ vh) {
    __shared__ float wq[16][17], wk[16][17], wv[16][17];
    __shared__ float rq[4][64], rk[4][64], rv[4][64];
    int tid = threadIdx.x;
    {
        int d = tid >> 4, e = tid & 15;
        wq[e][d] = Wq[tid];
        wk[e][d] = Wk[tid];
        wv[e][d] = Wv[tid];
    }
    int g = tid >> 6, c = tid & 63;
    int row = blockIdx.x * 4 + g;
    rq[g][c] = q[row * 64 + c];
    rk[g][c] = k[row * 64 + c];
    rv[g][c] = v[row * 64 + c];
    __syncthreads();
    int hh = c >> 4, d = c & 15;
    float sq = 0.f, sk = 0.f, sv = 0.f;
#pragma unroll
    for (int e = 0; e < 16; e++) {
        sq += rq[g][hh * 16 + e] * wq[e][d];
        sk += rk[g][hh * 16 + e] * wk[e][d];
        sv += rv[g][hh * 16 + e] * wv[e][d];
    }
    int n = row / TT, t = row % TT;
    int o = ((t * HH + hh) * NN + n) * HD + d;
    qh[o] = sq; kh[o] = sk; vh[o] = sv;
}

// ---------------------------------------------------------------------------
// Node-attention. One (t,h) per CTA, 2 q-rows per thread, 256 threads.
// Scores are tiny (~0.03 in log2 units) so no max-tracking needed.
// ---------------------------------------------------------------------------
__global__ void attn_kernel(const float* __restrict__ qh, const float* __restrict__ kh,
                            const float* __restrict__ vh, float* __restrict__ attn) {
    extern __shared__ float sm[];
    float* Ks = sm;
    float* Vs = sm + NN * HD;
    int th = blockIdx.x;
    int t = th >> 2, h = th & 3;
    size_t base = (size_t)th * (NN * HD);
    {
        const float4* k4 = reinterpret_cast<const float4*>(kh + base);
        const float4* v4 = reinterpret_cast<const float4*>(vh + base);
        float4* ks4 = reinterpret_cast<float4*>(Ks);
        float4* vs4 = reinterpret_cast<float4*>(Vs);
        for (int i = threadIdx.x; i < NN * HD / 4; i += 256) {
            ks4[i] = k4[i];
            vs4[i] = v4[i];
        }
    }
    __syncthreads();

    const float SCL = 0.125f * 1.44269504088896f;
    int q0 = threadIdx.x * 2;
    float qa[16], qb[16];
#pragma unroll
    for (int i = 0; i < 4; i++) {
        float4 a = reinterpret_cast<const float4*>(qh + base + q0 * 16)[i];
        float4 b = reinterpret_cast<const float4*>(qh + base + (q0 + 1) * 16)[i];
        qa[i*4+0] = a.x * SCL; qa[i*4+1] = a.y * SCL; qa[i*4+2] = a.z * SCL; qa[i*4+3] = a.w * SCL;
        qb[i*4+0] = b.x * SCL; qb[i*4+1] = b.y * SCL; qb[i*4+2] = b.z * SCL; qb[i*4+3] = b.w * SCL;
    }

    float la = 0.f, lb = 0.f;
    float acca[16], accb[16];
#pragma unroll
    for (int d = 0; d < 16; d++) { acca[d] = 0.f; accb[d] = 0.f; }

    for (int k = 0; k < NN; k++) {
        float kr[16];
#pragma unroll
        for (int i = 0; i < 4; i++) {
            float4 kk = reinterpret_cast<const float4*>(Ks + k * 16)[i];
            kr[i*4+0] = kk.x; kr[i*4+1] = kk.y; kr[i*4+2] = kk.z; kr[i*4+3] = kk.w;
        }
        float sa = 0.f, sb = 0.f;
#pragma unroll
        for (int d = 0; d < 16; d++) { sa += qa[d] * kr[d]; sb += qb[d] * kr[d]; }
        float pa = exp2f(sa), pb = exp2f(sb);
        la += pa; lb += pb;
#pragma unroll
        for (int i = 0; i < 4; i++) {
            float4 vv = reinterpret_cast<const float4*>(Vs + k * 16)[i];
            acca[i*4+0] += pa * vv.x; acca[i*4+1] += pa * vv.y;
            acca[i*4+2] += pa * vv.z; acca[i*4+3] += pa * vv.w;
            accb[i*4+0] += pb * vv.x; accb[i*4+1] += pb * vv.y;
            accb[i*4+2] += pb * vv.z; accb[i*4+3] += pb * vv.w;
        }
    }
    float ia = 1.f / la, ib = 1.f / lb;
    float* oa = attn + ((size_t)q0 * TT + t) * CC + h * HD;
    float* ob = attn + ((size_t)(q0 + 1) * TT + t) * CC + h * HD;
#pragma unroll
    for (int i = 0; i < 4; i++) {
        float4 wa, wb;
        wa.x = acca[i*4+0]*ia; wa.y = acca[i*4+1]*ia; wa.z = acca[i*4+2]*ia; wa.w = acca[i*4+3]*ia;
        wb.x = accb[i*4+0]*ib; wb.y = accb[i*4+1]*ib; wb.z = accb[i*4+2]*ib; wb.w = accb[i*4+3]*ib;
        reinterpret_cast<float4*>(oa)[i] = wa;
        reinterpret_cast<float4*>(ob)[i] = wb;
    }
}

// ---------------------------------------------------------------------------
// 3xTF32 split-precision wmma GEMM with fused epilogues.
//   x = hi + lo; acc += hi*hi' + hi*lo' + lo*hi'  (fp32-level accuracy)
//   Y[M,N] = A[M,K] @ op(B)
//   BROW=true : B is [K,N] row-major (GCN spatial)
//   BROW=false: B is W[N,K] row-major, op = transpose (nn.Linear)
//   ANORM: normalize A on load: (a - stats[0]) * stats[1]
//   EPI: 0=none, 1=bias(col%BMOD)+relu, 2=bias(col%BMOD),
//        3=bias+residual(R)+LayerNorm(P1=gamma,P2=beta)  [N==64]
//        4=gate: zb=acc+bias; g=sigmoid(R+zb); Y=g*P1+(1-g)*P2  [N==64]
// ---------------------------------------------------------------------------
template<int BM, int BN, int BK, int WM, int WN, bool BROW, bool ANORM, int EPI, int BMOD>
__global__ void gemm_tf32(const float* __restrict__ A, const float* __restrict__ B,
                          const float* __restrict__ bias, const float* __restrict__ R,
                          const float* __restrict__ P1, const float* __restrict__ P2,
                          const float* __restrict__ stats,
                          float* __restrict__ Y, int M, int N, int K) {
    extern __shared__ float smem[];
    constexpr int LDA = BK + 4;
    constexpr int LDB = BROW ? (BN + 4) : (BK + 4);
    constexpr int LDO = BN + 4;
    constexpr int SZA = BM * LDA;
    constexpr int SZB = BROW ? (BK * LDB) : (BN * LDB);
    constexpr int WARPS_M = BM / WM;
    constexpr int WARPS_N = BN / WN;
    constexpr int NTHR = WARPS_M * WARPS_N * 32;
    constexpr int FM = WM / 16;
    constexpr int FN = WN / 16;

    float* sAh = smem;
    float* sAl = smem + SZA;
    float* sBh = smem + 2 * SZA;
    float* sBl = smem + 2 * SZA + SZB;

    const int tid = threadIdx.x;
    const int warp = tid >> 5;
    const int wm = warp % WARPS_M;
    const int wn = warp / WARPS_M;
    const int rowBase = blockIdx.y * BM;
    const int colBase = blockIdx.x * BN;

    float s0 = 0.f, s1 = 1.f;
    if (ANORM) { s0 = stats[0]; s1 = stats[1]; }

    wmma::fragment<wmma::accumulator, 16, 16, 8, float> acc[FM][FN];
#pragma unroll
    for (int i = 0; i < FM; i++)
#pragma unroll
        for (int j = 0; j < FN; j++) wmma::fill_fragment(acc[i][j], 0.f);

    for (int k0 = 0; k0 < K; k0 += BK) {
        // stage A (with optional InstanceNorm), hi/lo split
        {
            constexpr int V = BM * BK / 4;
#pragma unroll
            for (int idx = tid; idx < V; idx += NTHR) {
                int m = idx / (BK / 4);
                int kq = (idx % (BK / 4)) * 4;
                float4 v4 = *reinterpret_cast<const float4*>(&A[(size_t)(rowBase + m) * K + k0 + kq]);
                if (ANORM) {
                    v4.x = (v4.x - s0) * s1; v4.y = (v4.y - s0) * s1;
                    v4.z = (v4.z - s0) * s1; v4.w = (v4.w - s0) * s1;
                }
                float4 h, l;
                h.x = wmma::__float_to_tf32(v4.x); l.x = wmma::__float_to_tf32(v4.x - h.x);
                h.y = wmma::__float_to_tf32(v4.y); l.y = wmma::__float_to_tf32(v4.y - h.y);
                h.z = wmma::__float_to_tf32(v4.z); l.z = wmma::__float_to_tf32(v4.z - h.z);
                h.w = wmma::__float_to_tf32(v4.w); l.w = wmma::__float_to_tf32(v4.w - h.w);
                *reinterpret_cast<float4*>(&sAh[m * LDA + kq]) = h;
                *reinterpret_cast<float4*>(&sAl[m * LDA + kq]) = l;
            }
        }
        // stage B hi/lo
        if (BROW) {
            constexpr int V = BK * BN / 4;
#pragma unroll
            for (int idx = tid; idx < V; idx += NTHR) {
                int kk = idx / (BN / 4);
                int nq = (idx % (BN / 4)) * 4;
                float4 v4 = *reinterpret_cast<const float4*>(&B[(size_t)(k0 + kk) * N + colBase + nq]);
                float4 h, l;
                h.x = wmma::__float_to_tf32(v4.x); l.x = wmma::__float_to_tf32(v4.x - h.x);
                h.y = wmma::__float_to_tf32(v4.y); l.y = wmma::__float_to_tf32(v4.y - h.y);
                h.z = wmma::__float_to_tf32(v4.z); l.z = wmma::__float_to_tf32(v4.z - h.z);
                h.w = wmma::__float_to_tf32(v4.w); l.w = wmma::__float_to_tf32(v4.w - h.w);
                *reinterpret_cast<float4*>(&sBh[kk * LDB + nq]) = h;
                *reinterpret_cast<float4*>(&sBl[kk * LDB + nq]) = l;
            }
        } else {
            constexpr int V = BN * BK / 4;
#pragma unroll
            for (int idx = tid; idx < V; idx += NTHR) {
                int n = idx / (BK / 4);
                int kq = (idx % (BK / 4)) * 4;
                float4 v4 = *reinterpret_cast<const float4*>(&B[(size_t)(colBase + n) * K + k0 + kq]);
                float4 h, l;
                h.x = wmma::__float_to_tf32(v4.x); l.x = wmma::__float_to_tf32(v4.x - h.x);
                h.y = wmma::__float_to_tf32(v4.y); l.y = wmma::__float_to_tf32(v4.y - h.y);
                h.z = wmma::__float_to_tf32(v4.z); l.z = wmma::__float_to_tf32(v4.z - h.z);
                h.w = wmma::__float_to_tf32(v4.w); l.w = wmma::__float_to_tf32(v4.w - h.w);
                *reinterpret_cast<float4*>(&sBh[n * LDB + kq]) = h;
                *reinterpret_cast<float4*>(&sBl[n * LDB + kq]) = l;
            }
        }
        __syncthreads();

        using BLayout = typename std::conditional<BROW, wmma::row_major, wmma::col_major>::type;
#pragma unroll
        for (int kk = 0; kk < BK; kk += 8) {
            wmma::fragment<wmma::matrix_a, 16, 16, 8, wmma::precision::tf32, wmma::row_major> afh[FM], afl[FM];
#pragma unroll
            for (int i = 0; i < FM; i++) {
                wmma::load_matrix_sync(afh[i], &sAh[(wm * WM + i * 16) * LDA + kk], LDA);
                wmma::load_matrix_sync(afl[i], &sAl[(wm * WM + i * 16) * LDA + kk], LDA);
            }
            wmma::fragment<wmma::matrix_b, 16, 16, 8, wmma::precision::tf32, BLayout> bfh[FN], bfl[FN];
#pragma unroll
            for (int j = 0; j < FN; j++) {
                if (BROW) {
                    wmma::load_matrix_sync(bfh[j], &sBh[kk * LDB + wn * WN + j * 16], LDB);
                    wmma::load_matrix_sync(bfl[j], &sBl[kk * LDB + wn * WN + j * 16], LDB);
                } else {
                    wmma::load_matrix_sync(bfh[j], &sBh[(wn * WN + j * 16) * LDB + kk], LDB);
                    wmma::load_matrix_sync(bfl[j], &sBl[(wn * WN + j * 16) * LDB + kk], LDB);
                }
            }
#pragma unroll
            for (int i = 0; i < FM; i++)
#pragma unroll
                for (int j = 0; j < FN; j++) {
                    wmma::mma_sync(acc[i][j], afh[i], bfl[j], acc[i][j]);
                    wmma::mma_sync(acc[i][j], afl[i], bfh[j], acc[i][j]);
                    wmma::mma_sync(acc[i][j], afh[i], bfh[j], acc[i][j]);
                }
        }
        __syncthreads();
    }

    // ---- epilogue via smem roundtrip ----
    float* sO = smem;
#pragma unroll
    for (int i = 0; i < FM; i++)
#pragma unroll
        for (int j = 0; j < FN; j++)
            wmma::store_matrix_sync(&sO[(wm * WM + i * 16) * LDO + wn * WN + j * 16],
                                    acc[i][j], LDO, wmma::mem_row_major);
    __syncthreads();

    if (EPI == 3) {
        // bias + residual, then LayerNorm over the (full) 64-wide row
        for (int idx = tid; idx < BM * BN; idx += NTHR) {
            int m = idx / BN, c = idx % BN;
            sO[m * LDO + c] += bias[c] + R[(size_t)(rowBase + m) * 64 + c];
        }
        __syncthreads();
        if (tid < BM) {
            int r = rowBase + tid;
            float mean = 0.f;
#pragma unroll
            for (int c = 0; c < 64; c++) mean += sO[tid * LDO + c];
            mean *= (1.f / 64.f);
            float var = 0.f;
#pragma unroll
            for (int c = 0; c < 64; c++) {
                float d = sO[tid * LDO + c] - mean;
                var += d * d;
            }
            float rs = rsqrtf(var * (1.f / 64.f) + EPS);
#pragma unroll
            for (int c = 0; c < 64; c++)
                Y[(size_t)r * 64 + c] = (sO[tid * LDO + c] - mean) * rs * P1[c] + P2[c];
        }
    } else {
        for (int idx = tid; idx < BM * BN; idx += NTHR) {
            int m = idx / BN, c = idx % BN;
            int r = rowBase + m, col = colBase + c;
            float v = sO[m * LDO + c];
            if (EPI == 1) v = fmaxf(v + bias[col % BMOD], 0.f);
            if (EPI == 2) v = v + bias[col % BMOD];
            if (EPI == 4) {
                v += bias[col];
                float xg = R[(size_t)r * N + col] + v;
                float s = 1.f / (1.f + __expf(-xg));
                v = s * P1[(size_t)r * N + col] + (1.f - s) * P2[(size_t)r * N + col];
            }
            Y[(size_t)r * N + col] = v;
        }
    }
}

// ---------------------------------------------------------------------------
extern "C" void kernel_launch(void* const* d_in, const int* in_sizes, int n_in,
                              void* d_out, int out_size) {
    const float* value = (const float*)d_in[0];
    const float* key_t = (const float*)d_in[1];
    const float* query = (const float*)d_in[2];
    const float* adj   = (const float*)d_in[3];
    const float* Wv    = (const float*)d_in[4];
    const float* Wk    = (const float*)d_in[5];
    const float* Wq    = (const float*)d_in[6];
    const float* Wo    = (const float*)d_in[7];
    const float* bo    = (const float*)d_in[8];
    const float* g1    = (const float*)d_in[9];
    const float* b1    = (const float*)d_in[10];
    const float* g2    = (const float*)d_in[11];
    const float* b2    = (const float*)d_in[12];
    const float* Wf1   = (const float*)d_in[13];
    const float* bf1   = (const float*)d_in[14];
    const float* Wf2   = (const float*)d_in[15];
    const float* bf2   = (const float*)d_in[16];
    const float* Wg1   = (const float*)d_in[17];
    const float* bg1   = (const float*)d_in[18];
    const float* Wg2   = (const float*)d_in[19];
    const float* bg2   = (const float*)d_in[20];
    const float* Wo1   = (const float*)d_in[21];
    const float* bo1   = (const float*)d_in[22];
    const float* Wo2   = (const float*)d_in[23];
    const float* bo2   = (const float*)d_in[24];
    float* out = (float*)d_out;

    float* base;
    cudaGetSymbolAddress((void**)&base, g_scratch);
    float* qh    = base + OFF_QH;
    float* kh    = base + OFF_KH;
    float* vh    = base + OFF_VH;
    float* attnb = base + OFF_ATT;
    float* x     = base + OFF_X;
    float* hbuf  = base + OFF_H;
    float* out1  = base + OFF_OUT1;
    float* t1    = base + OFF_T1;
    float* t2    = base + OFF_T2;
    float* t3    = base + OFF_T3;
    float* out2  = base + OFF_OUT2;
    float* za    = base + OFF_ZA;
    float* part  = base + OFF_PART;
    float* stat  = base + OFF_STAT;

    // GEMM instantiations
    auto G_LN   = gemm_tf32<128, 64, 32, 32, 32, false, false, 3, 64>;   // bias+res+LN
    auto G_FF1  = gemm_tf32<128, 128, 32, 64, 32, false, false, 1, 256>; // bias+relu
    auto G_P    = gemm_tf32<128, 64, 32, 32, 32, false, false, 0, 64>;   // plain
    auto G_GCN1 = gemm_tf32<128, 128, 32, 64, 32, true, true, 1, 64>;    // anorm+bias+relu
    auto G_GCN2 = gemm_tf32<128, 128, 32, 64, 32, true, true, 2, 64>;    // anorm+bias
    auto G_B    = gemm_tf32<128, 64, 32, 32, 32, false, false, 2, 64>;   // bias
    auto G_GATE = gemm_tf32<128, 64, 32, 32, 32, false, false, 4, 64>;   // gate fusion

    // smem sizes (bytes): max(hi/lo staging, epilogue tile)
    // BN=64  : stage = 2*(128*36) + 2*(64*36) = 13824 fl = 55296 B; epi 34816 B
    // FF1    : stage = 2*(128*36) + 2*(128*36) = 18432 fl = 73728 B; epi 67584 B
    // GCN    : stage = 2*(128*36) + 2*(32*132) = 17664 fl = 70656 B; epi 67584 B
    const int SM_SMALL = 55296;
    const int SM_FF1   = 73728;
    const int SM_GCN   = 70656;

    cudaFuncSetAttribute(G_LN,   cudaFuncAttributeMaxDynamicSharedMemorySize, SM_SMALL);
    cudaFuncSetAttribute(G_P,    cudaFuncAttributeMaxDynamicSharedMemorySize, SM_SMALL);
    cudaFuncSetAttribute(G_B,    cudaFuncAttributeMaxDynamicSharedMemorySize, SM_SMALL);
    cudaFuncSetAttribute(G_GATE, cudaFuncAttributeMaxDynamicSharedMemorySize, SM_SMALL);
    cudaFuncSetAttribute(G_FF1,  cudaFuncAttributeMaxDynamicSharedMemorySize, SM_FF1);
    cudaFuncSetAttribute(G_GCN1, cudaFuncAttributeMaxDynamicSharedMemorySize, SM_GCN);
    cudaFuncSetAttribute(G_GCN2, cudaFuncAttributeMaxDynamicSharedMemorySize, SM_GCN);
    cudaFuncSetAttribute(attn_kernel, cudaFuncAttributeMaxDynamicSharedMemorySize, 65536);

    // adj InstanceNorm stats
    adj_rowred_kernel<<<512, 256>>>(adj, part);
    adj_final_kernel<<<1, 256>>>(part, stat);

    // head projections
    proj_kernel<<<MM / 4, 256>>>(query, key_t, value, Wq, Wk, Wv, qh, kh, vh);

    // node-attention
    attn_kernel<<<TT * HH, 256, 65536>>>(qh, kh, vh, attnb);

    // z1 = attn@Wo^T + bo + query; x = LN1(z1)
    G_LN<<<dim3(1, MM / 128), 256, SM_SMALL>>>(attnb, Wo, bo, query, g1, b1, nullptr, x, MM, 64, 64);

    // FFN: hbuf = relu(x@Wf1^T + bf1); out1 = LN2(hbuf@Wf2^T + bf2 + x)
    G_FF1<<<dim3(2, MM / 128), 256, SM_FF1>>>(x, Wf1, bf1, nullptr, nullptr, nullptr, nullptr, hbuf, MM, 256, 64);
    G_LN<<<dim3(1, MM / 128), 256, SM_SMALL>>>(hbuf, Wf2, bf2, x, g2, b2, nullptr, out1, MM, 64, 256);

    // GCN: t1 = query@Wg1^T; t2 = relu(adjn@t1 + bg1); t3 = t2@Wg2^T; out2 = adjn@t3 + bg2
    G_P<<<dim3(1, MM / 128), 256, SM_SMALL>>>(query, Wg1, nullptr, nullptr, nullptr, nullptr, nullptr, t1, MM, 64, 64);
    G_GCN1<<<dim3(32, 4), 256, SM_GCN>>>(adj, t1, bg1, nullptr, nullptr, nullptr, stat, t2, 512, 4096, 512);
    G_P<<<dim3(1, MM / 128), 256, SM_SMALL>>>(t2, Wg2, nullptr, nullptr, nullptr, nullptr, nullptr, t3, MM, 64, 64);
    G_GCN2<<<dim3(32, 4), 256, SM_GCN>>>(adj, t3, bg2, nullptr, nullptr, nullptr, stat, out2, 512, 4096, 512);

    // gating: za = out1@Wo1^T + bo1; out = sig(za + out2@Wo2^T + bo2)*out1 + (1-sig)*out2
    G_B<<<dim3(1, MM / 128), 256, SM_SMALL>>>(out1, Wo1, bo1, nullptr, nullptr, nullptr, nullptr, za, MM, 64, 64);
    G_GATE<<<dim3(1, MM / 128), 256, SM_SMALL>>>(out2, Wo2, bo2, za, out1, out2, nullptr, out, MM, 64, 64);
}

// round 6
// speedup vs baseline: 1.5830x; 1.5830x over previous
#include <cuda_runtime.h>
#include <math.h>

typedef unsigned long long ull;

// Problem dims
#define NN 512
#define TT 64
#define CC 64
#define HH 4
#define HD 16
#define MM (NN*TT)      // 32768 rows
#define EPS 1e-5f

// ---------------------------------------------------------------------------
// Scratch
// ---------------------------------------------------------------------------
#define SZ 2097152
#define OFF_QH   0
#define OFF_KH   (1*SZ)
#define OFF_VH   (2*SZ)
#define OFF_ATT  (3*SZ)
#define OFF_X    (4*SZ)
#define OFF_H    (5*SZ)     // size 4*SZ: hbuf, also attention partials
#define OFF_OUT1 (9*SZ)
#define OFF_T1   (10*SZ)
#define OFF_T2   (11*SZ)
#define OFF_T3   (12*SZ)
#define OFF_OUT2 (13*SZ)
#define OFF_ZA   (14*SZ)
#define OFF_PART (15*SZ)
#define OFF_STAT (15*SZ + 1024)
#define SCRATCH_TOTAL (15*SZ + 1024 + 16)

__device__ __align__(16) float g_scratch[SCRATCH_TOTAL];

// ---------------------------------------------------------------------------
// Packed f32x2 helpers (Blackwell native)
// ---------------------------------------------------------------------------
__device__ __forceinline__ ull pk2(float x, float y) {
    ull r; asm("mov.b64 %0, {%1, %2};" : "=l"(r) : "f"(x), "f"(y)); return r;
}
__device__ __forceinline__ void upk2(ull v, float& x, float& y) {
    asm("mov.b64 {%0, %1}, %2;" : "=f"(x), "=f"(y) : "l"(v));
}
__device__ __forceinline__ ull ffma2(ull a, ull b, ull c) {
    ull d; asm("fma.rn.f32x2 %0, %1, %2, %3;" : "=l"(d) : "l"(a), "l"(b), "l"(c)); return d;
}

// ---------------------------------------------------------------------------
// adj InstanceNorm stats (normalization fused into GCN A-staging)
// ---------------------------------------------------------------------------
__global__ void adj_rowred_kernel(const float* __restrict__ adj, float* __restrict__ part) {
    __shared__ float s1[256], s2[256];
    int r = blockIdx.x, t = threadIdx.x;
    float a = adj[r * 512 + t];
    float b = adj[r * 512 + 256 + t];
    s1[t] = a + b;
    s2[t] = a * a + b * b;
    __syncthreads();
    for (int st = 128; st > 0; st >>= 1) {
        if (t < st) { s1[t] += s1[t + st]; s2[t] += s2[t + st]; }
        __syncthreads();
    }
    if (t == 0) { part[r] = s1[0]; part[512 + r] = s2[0]; }
}

__global__ void adj_final_kernel(const float* __restrict__ part, float* __restrict__ stats) {
    __shared__ float s1[256], s2[256];
    int t = threadIdx.x;
    s1[t] = part[t] + part[t + 256];
    s2[t] = part[512 + t] + part[512 + t + 256];
    __syncthreads();
    for (int st = 128; st > 0; st >>= 1) {
        if (t < st) { s1[t] += s1[t + st]; s2[t] += s2[t + st]; }
        __syncthreads();
    }
    if (t == 0) {
        float mean = s1[0] * (1.0f / 262144.0f);
        float var  = s2[0] * (1.0f / 262144.0f) - mean * mean;
        stats[0] = mean;
        stats[1] = rsqrtf(var + EPS);
    }
}

// ---------------------------------------------------------------------------
// Per-head projections q/k/v -> [T,H,N,HD] (conflict-free smem weights)
// ---------------------------------------------------------------------------
__global__ void proj_kernel(const float* __restrict__ q, const float* __restrict__ k,
                            const float* __restrict__ v,
                            const float* __restrict__ Wq, const float* __restrict__ Wk,
                            const float* __restrict__ Wv,
                            float* __restrict__ qh, float* __restrict__ kh,
                            float* __restrict__ vh) {
    __shared__ float wq[16][17], wk[16][17], wv[16][17];
    __shared__ float rq[4][64], rk[4][64], rv[4][64];
    int tid = threadIdx.x;
    {
        int d = tid >> 4, e = tid & 15;
        wq[e][d] = Wq[tid];
        wk[e][d] = Wk[tid];
        wv[e][d] = Wv[tid];
    }
    int g = tid >> 6, c = tid & 63;
    int row = blockIdx.x * 4 + g;
    rq[g][c] = q[row * 64 + c];
    rk[g][c] = k[row * 64 + c];
    rv[g][c] = v[row * 64 + c];
    __syncthreads();
    int hh = c >> 4, d = c & 15;
    float sq = 0.f, sk = 0.f, sv = 0.f;
#pragma unroll
    for (int e = 0; e < 16; e++) {
        sq += rq[g][hh * 16 + e] * wq[e][d];
        sk += rk[g][hh * 16 + e] * wk[e][d];
        sv += rv[g][hh * 16 + e] * wv[e][d];
    }
    int n = row / TT, t = row % TT;
    int o = ((t * HH + hh) * NN + n) * HD + d;
    qh[o] = sq; kh[o] = sk; vh[o] = sv;
}

// ---------------------------------------------------------------------------
// Node-attention partials, packed f32x2, split-K=2.
// grid (256, 2): blockIdx.x = (t,h), blockIdx.y = k-chunk. 256 threads,
// 2 q-rows per thread. K/V chunk [256,16] in smem (32KB). Since there is no
// running max (scores tiny), partial (acc, l) are directly additive.
// ---------------------------------------------------------------------------
__global__ void attn_part_kernel(const float* __restrict__ qh, const float* __restrict__ kh,
                                 const float* __restrict__ vh,
                                 float* __restrict__ pacc, float* __restrict__ pl) {
    __shared__ float Ks[256 * HD];
    __shared__ float Vs[256 * HD];
    int th = blockIdx.x;
    int chunk = blockIdx.y;
    size_t base = (size_t)th * (NN * HD);
    size_t cbase = base + (size_t)chunk * (256 * HD);
    {
        const float4* k4 = reinterpret_cast<const float4*>(kh + cbase);
        const float4* v4 = reinterpret_cast<const float4*>(vh + cbase);
        float4* ks4 = reinterpret_cast<float4*>(Ks);
        float4* vs4 = reinterpret_cast<float4*>(Vs);
        for (int i = threadIdx.x; i < 256 * HD / 4; i += 256) {
            ks4[i] = k4[i];
            vs4[i] = v4[i];
        }
    }
    __syncthreads();

    const float SCL = 0.125f * 1.44269504088896f;  // 1/sqrt(C) * log2(e)
    int q0 = threadIdx.x * 2;
    ull qp0[8], qp1[8];
#pragma unroll
    for (int i = 0; i < 4; i++) {
        float4 a = reinterpret_cast<const float4*>(qh + base + (size_t)q0 * HD)[i];
        float4 b = reinterpret_cast<const float4*>(qh + base + (size_t)(q0 + 1) * HD)[i];
        qp0[i * 2 + 0] = pk2(a.x * SCL, a.y * SCL);
        qp0[i * 2 + 1] = pk2(a.z * SCL, a.w * SCL);
        qp1[i * 2 + 0] = pk2(b.x * SCL, b.y * SCL);
        qp1[i * 2 + 1] = pk2(b.z * SCL, b.w * SCL);
    }

    ull ac0[8], ac1[8];
    ull z = pk2(0.f, 0.f);
#pragma unroll
    for (int d = 0; d < 8; d++) { ac0[d] = z; ac1[d] = z; }
    float l0 = 0.f, l1 = 0.f;

    for (int k = 0; k < 256; k++) {
        ull kr[8];
        {
            const ulonglong2* kp = reinterpret_cast<const ulonglong2*>(Ks + k * HD);
#pragma unroll
            for (int i = 0; i < 4; i++) {
                ulonglong2 t2 = kp[i];
                kr[i * 2] = t2.x; kr[i * 2 + 1] = t2.y;
            }
        }
        ull s0 = z, s1 = z;
#pragma unroll
        for (int d = 0; d < 8; d++) {
            s0 = ffma2(qp0[d], kr[d], s0);
            s1 = ffma2(qp1[d], kr[d], s1);
        }
        float ax, ay, bx, by;
        upk2(s0, ax, ay);
        upk2(s1, bx, by);
        float p0 = exp2f(ax + ay);
        float p1 = exp2f(bx + by);
        l0 += p0; l1 += p1;
        ull pp0 = pk2(p0, p0), pp1 = pk2(p1, p1);
        {
            const ulonglong2* vp = reinterpret_cast<const ulonglong2*>(Vs + k * HD);
#pragma unroll
            for (int i = 0; i < 4; i++) {
                ulonglong2 t2 = vp[i];
                ac0[i * 2]     = ffma2(pp0, t2.x, ac0[i * 2]);
                ac0[i * 2 + 1] = ffma2(pp0, t2.y, ac0[i * 2 + 1]);
                ac1[i * 2]     = ffma2(pp1, t2.x, ac1[i * 2]);
                ac1[i * 2 + 1] = ffma2(pp1, t2.y, ac1[i * 2 + 1]);
            }
        }
    }

    // store partials (unnormalized)
    size_t pbase0 = ((size_t)(chunk * 256 + th) * 512 + q0) * HD;
    size_t pbase1 = pbase0 + HD;
#pragma unroll
    for (int i = 0; i < 4; i++) {
        float x0, y0, x1, y1;
        float4 o;
        upk2(ac0[i * 2], x0, y0); upk2(ac0[i * 2 + 1], x1, y1);
        o.x = x0; o.y = y0; o.z = x1; o.w = y1;
        reinterpret_cast<float4*>(pacc + pbase0)[i] = o;
        upk2(ac1[i * 2], x0, y0); upk2(ac1[i * 2 + 1], x1, y1);
        o.x = x0; o.y = y0; o.z = x1; o.w = y1;
        reinterpret_cast<float4*>(pacc + pbase1)[i] = o;
    }
    pl[(size_t)chunk * 131072 + th * 512 + q0]     = l0;
    pl[(size_t)chunk * 131072 + th * 512 + q0 + 1] = l1;
}

// Combine the 2 k-chunks, normalize, write to [N,T,C] layout.
__global__ void attn_combine_kernel(const float* __restrict__ pacc,
                                    const float* __restrict__ pl,
                                    float* __restrict__ attn) {
    int th = blockIdx.x;
    int t = th >> 2, h = th & 3;
#pragma unroll
    for (int j = 0; j < 2; j++) {
        int q = threadIdx.x * 2 + j;
        size_t i0 = ((size_t)(0 * 256 + th) * 512 + q) * HD;
        size_t i1 = ((size_t)(1 * 256 + th) * 512 + q) * HD;
        float l = pl[th * 512 + q] + pl[131072 + th * 512 + q];
        float inv = 1.f / l;
        float* o = attn + ((size_t)q * TT + t) * CC + h * HD;
#pragma unroll
        for (int i = 0; i < 4; i++) {
            float4 a = reinterpret_cast<const float4*>(pacc + i0)[i];
            float4 b = reinterpret_cast<const float4*>(pacc + i1)[i];
            float4 w;
            w.x = (a.x + b.x) * inv; w.y = (a.y + b.y) * inv;
            w.z = (a.z + b.z) * inv; w.w = (a.w + b.w) * inv;
            reinterpret_cast<float4*>(o)[i] = w;
        }
    }
}

// ---------------------------------------------------------------------------
// fp32 packed-f32x2 GEMM, 64x64 tile, BK=64, 256 threads, fused epilogues.
//   Y[M,N] = A[M,K] @ op(B)
//   BROW=true : B is [K,N] row-major (GCN spatial)
//   BROW=false: B is W[N,K] row-major, op = transpose (nn.Linear)
//   ANORM: normalize A on load: (a - stats[0]) * stats[1]
//   EPI: 0=none, 1=bias+relu, 2=bias,
//        3=bias+residual(R)+LayerNorm(P1=gamma,P2=beta)  [N==64, grid.x==1]
//        4=gate: zb=acc+bias; g=sigmoid(R+zb); Y=g*P1+(1-g)*P2  [N==64]
//   Microtile: thread (tx,ty) -> rows ty+16i (i<4), cols 4*tx..4*tx+3.
//   B staged k-major in smem so column pairs are contiguous (f32x2 loads).
// ---------------------------------------------------------------------------
template<int EPI, bool BROW, bool ANORM, int BMOD>
__global__ void __launch_bounds__(256) gemm64(
        const float* __restrict__ A, const float* __restrict__ B,
        const float* __restrict__ bias, const float* __restrict__ R,
        const float* __restrict__ P1, const float* __restrict__ P2,
        const float* __restrict__ stats,
        float* __restrict__ Y, int M, int N, int K) {
    __shared__ float As[64][68];
    __shared__ float Bs[64][68];
    int tid = threadIdx.x;
    int tx = tid & 15, ty = tid >> 4;
    int rowBase = blockIdx.y * 64, colBase = blockIdx.x * 64;

    float s0 = 0.f, s1 = 1.f;
    if (ANORM) { s0 = stats[0]; s1 = stats[1]; }

    ull acc2[4][2];
    ull z = pk2(0.f, 0.f);
#pragma unroll
    for (int i = 0; i < 4; i++) { acc2[i][0] = z; acc2[i][1] = z; }

    for (int k0 = 0; k0 < K; k0 += 64) {
        // stage A [64 rows x 64 k] (optionally InstanceNorm'd)
#pragma unroll
        for (int it = 0; it < 4; it++) {
            int idx = tid + it * 256;
            int i = idx >> 4;
            int j = (idx & 15) * 4;
            float4 v = *reinterpret_cast<const float4*>(&A[(size_t)(rowBase + i) * K + k0 + j]);
            if (ANORM) {
                v.x = (v.x - s0) * s1; v.y = (v.y - s0) * s1;
                v.z = (v.z - s0) * s1; v.w = (v.w - s0) * s1;
            }
            *reinterpret_cast<float4*>(&As[i][j]) = v;
        }
        // stage B k-major: Bs[kk][col]
        if (BROW) {
#pragma unroll
            for (int it = 0; it < 4; it++) {
                int idx = tid + it * 256;
                int kk = idx >> 4;
                int j = (idx & 15) * 4;
                float4 v = *reinterpret_cast<const float4*>(&B[(size_t)(k0 + kk) * N + colBase + j]);
                *reinterpret_cast<float4*>(&Bs[kk][j]) = v;
            }
        } else {
            // transpose-stage W[N,K]: Bs[kk][n] = W[colBase+n][k0+kk]
#pragma unroll
            for (int it = 0; it < 4; it++) {
                int idx = tid + it * 256;
                int n = idx & 63;
                int kq = (idx >> 6) * 4;
                float4 v = *reinterpret_cast<const float4*>(&B[(size_t)(colBase + n) * K + k0 + kq]);
                Bs[kq + 0][n] = v.x;
                Bs[kq + 1][n] = v.y;
                Bs[kq + 2][n] = v.z;
                Bs[kq + 3][n] = v.w;
            }
        }
        __syncthreads();

#pragma unroll 8
        for (int e = 0; e < 64; e++) {
            ull b0 = *reinterpret_cast<const ull*>(&Bs[e][4 * tx]);
            ull b1 = *reinterpret_cast<const ull*>(&Bs[e][4 * tx + 2]);
#pragma unroll
            for (int i = 0; i < 4; i++) {
                float a = As[ty + 16 * i][e];
                ull a2 = pk2(a, a);
                acc2[i][0] = ffma2(a2, b0, acc2[i][0]);
                acc2[i][1] = ffma2(a2, b1, acc2[i][1]);
            }
        }
        __syncthreads();
    }

    // unpack accumulators
    float v[4][4];
#pragma unroll
    for (int i = 0; i < 4; i++) {
        upk2(acc2[i][0], v[i][0], v[i][1]);
        upk2(acc2[i][1], v[i][2], v[i][3]);
    }

    if (EPI == 3) {
        // bias + residual into smem (reuse As as [64][68] output tile), then LN
#pragma unroll
        for (int i = 0; i < 4; i++) {
            int rr = ty + 16 * i;
            float4 rz = *reinterpret_cast<const float4*>(&R[(size_t)(rowBase + rr) * 64 + 4 * tx]);
            float4 o;
            o.x = v[i][0] + bias[4 * tx + 0] + rz.x;
            o.y = v[i][1] + bias[4 * tx + 1] + rz.y;
            o.z = v[i][2] + bias[4 * tx + 2] + rz.z;
            o.w = v[i][3] + bias[4 * tx + 3] + rz.w;
            *reinterpret_cast<float4*>(&As[rr][4 * tx]) = o;
        }
        __syncthreads();
        int row = tid >> 2;
        int qq = (tid & 3) * 16;
        float sum = 0.f, sq = 0.f;
#pragma unroll
        for (int c = 0; c < 16; c++) {
            float x = As[row][qq + c];
            sum += x; sq += x * x;
        }
        sum += __shfl_xor_sync(0xffffffff, sum, 1);
        sum += __shfl_xor_sync(0xffffffff, sum, 2);
        sq  += __shfl_xor_sync(0xffffffff, sq, 1);
        sq  += __shfl_xor_sync(0xffffffff, sq, 2);
        float mean = sum * (1.f / 64.f);
        float var = sq * (1.f / 64.f) - mean * mean;
        float rs = rsqrtf(var + EPS);
#pragma unroll
        for (int c4 = 0; c4 < 4; c4++) {
            int c = qq + c4 * 4;
            float4 a = *reinterpret_cast<const float4*>(&As[row][c]);
            float4 g = *reinterpret_cast<const float4*>(&P1[c]);
            float4 bb = *reinterpret_cast<const float4*>(&P2[c]);
            float4 o;
            o.x = (a.x - mean) * rs * g.x + bb.x;
            o.y = (a.y - mean) * rs * g.y + bb.y;
            o.z = (a.z - mean) * rs * g.z + bb.z;
            o.w = (a.w - mean) * rs * g.w + bb.w;
            *reinterpret_cast<float4*>(&Y[(size_t)(rowBase + row) * 64 + c]) = o;
        }
    } else {
#pragma unroll
        for (int i = 0; i < 4; i++) {
            int r = rowBase + ty + 16 * i;
            int col0 = colBase + 4 * tx;
            float4 o;
            o.x = v[i][0]; o.y = v[i][1]; o.z = v[i][2]; o.w = v[i][3];
            if (EPI == 1 || EPI == 2 || EPI == 4) {
                o.x += bias[(col0 + 0) & (BMOD - 1)];
                o.y += bias[(col0 + 1) & (BMOD - 1)];
                o.z += bias[(col0 + 2) & (BMOD - 1)];
                o.w += bias[(col0 + 3) & (BMOD - 1)];
            }
            if (EPI == 1) {
                o.x = fmaxf(o.x, 0.f); o.y = fmaxf(o.y, 0.f);
                o.z = fmaxf(o.z, 0.f); o.w = fmaxf(o.w, 0.f);
            }
            if (EPI == 4) {
                float4 rz = *reinterpret_cast<const float4*>(&R[(size_t)r * N + col0]);
                float4 p1 = *reinterpret_cast<const float4*>(&P1[(size_t)r * N + col0]);
                float4 p2 = *reinterpret_cast<const float4*>(&P2[(size_t)r * N + col0]);
                float s;
                s = 1.f / (1.f + __expf(-(rz.x + o.x))); o.x = s * p1.x + (1.f - s) * p2.x;
                s = 1.f / (1.f + __expf(-(rz.y + o.y))); o.y = s * p1.y + (1.f - s) * p2.y;
                s = 1.f / (1.f + __expf(-(rz.z + o.z))); o.z = s * p1.z + (1.f - s) * p2.z;
                s = 1.f / (1.f + __expf(-(rz.w + o.w))); o.w = s * p1.w + (1.f - s) * p2.w;
            }
            *reinterpret_cast<float4*>(&Y[(size_t)r * N + col0]) = o;
        }
    }
}

// ---------------------------------------------------------------------------
extern "C" void kernel_launch(void* const* d_in, const int* in_sizes, int n_in,
                              void* d_out, int out_size) {
    const float* value = (const float*)d_in[0];
    const float* key_t = (const float*)d_in[1];
    const float* query = (const float*)d_in[2];
    const float* adj   = (const float*)d_in[3];
    const float* Wv    = (const float*)d_in[4];
    const float* Wk    = (const float*)d_in[5];
    const float* Wq    = (const float*)d_in[6];
    const float* Wo    = (const float*)d_in[7];
    const float* bo    = (const float*)d_in[8];
    const float* g1    = (const float*)d_in[9];
    const float* b1    = (const float*)d_in[10];
    const float* g2    = (const float*)d_in[11];
    const float* b2    = (const float*)d_in[12];
    const float* Wf1   = (const float*)d_in[13];
    const float* bf1   = (const float*)d_in[14];
    const float* Wf2   = (const float*)d_in[15];
    const float* bf2   = (const float*)d_in[16];
    const float* Wg1   = (const float*)d_in[17];
    const float* bg1   = (const float*)d_in[18];
    const float* Wg2   = (const float*)d_in[19];
    const float* bg2   = (const float*)d_in[20];
    const float* Wo1   = (const float*)d_in[21];
    const float* bo1   = (const float*)d_in[22];
    const float* Wo2   = (const float*)d_in[23];
    const float* bo2   = (const float*)d_in[24];
    float* out = (float*)d_out;

    float* base;
    cudaGetSymbolAddress((void**)&base, g_scratch);
    float* qh    = base + OFF_QH;
    float* kh    = base + OFF_KH;
    float* vh    = base + OFF_VH;
    float* attnb = base + OFF_ATT;
    float* x     = base + OFF_X;
    float* hbuf  = base + OFF_H;    // FFN hidden; also attention partials (earlier)
    float* pacc  = base + OFF_H;    // 4.2M floats
    float* pl    = base + OFF_H + 4194304;
    float* out1  = base + OFF_OUT1;
    float* t1    = base + OFF_T1;
    float* t2    = base + OFF_T2;
    float* t3    = base + OFF_T3;
    float* out2  = base + OFF_OUT2;
    float* za    = base + OFF_ZA;
    float* part  = base + OFF_PART;
    float* stat  = base + OFF_STAT;

    // adj InstanceNorm stats
    adj_rowred_kernel<<<512, 256>>>(adj, part);
    adj_final_kernel<<<1, 256>>>(part, stat);

    // head projections
    proj_kernel<<<MM / 4, 256>>>(query, key_t, value, Wq, Wk, Wv, qh, kh, vh);

    // node-attention: split-K partials + combine
    attn_part_kernel<<<dim3(TT * HH, 2), 256>>>(qh, kh, vh, pacc, pl);
    attn_combine_kernel<<<TT * HH, 256>>>(pacc, pl, attnb);

    // z1 = attn@Wo^T + bo + query; x = LN1(z1)
    gemm64<3, false, false, 64><<<dim3(1, MM / 64), 256>>>(
        attnb, Wo, bo, query, g1, b1, nullptr, x, MM, 64, 64);

    // FFN: hbuf = relu(x@Wf1^T + bf1); out1 = LN2(hbuf@Wf2^T + bf2 + x)
    gemm64<1, false, false, 256><<<dim3(4, MM / 64), 256>>>(
        x, Wf1, bf1, nullptr, nullptr, nullptr, nullptr, hbuf, MM, 256, 64);
    gemm64<3, false, false, 64><<<dim3(1, MM / 64), 256>>>(
        hbuf, Wf2, bf2, x, g2, b2, nullptr, out1, MM, 64, 256);

    // GCN: t1 = query@Wg1^T; t2 = relu(adjn@t1 + bg1); t3 = t2@Wg2^T; out2 = adjn@t3 + bg2
    gemm64<0, false, false, 64><<<dim3(1, MM / 64), 256>>>(
        query, Wg1, nullptr, nullptr, nullptr, nullptr, nullptr, t1, MM, 64, 64);
    gemm64<1, true, true, 64><<<dim3(64, 8), 256>>>(
        adj, t1, bg1, nullptr, nullptr, nullptr, stat, t2, 512, 4096, 512);
    gemm64<0, false, false, 64><<<dim3(1, MM / 64), 256>>>(
        t2, Wg2, nullptr, nullptr, nullptr, nullptr, nullptr, t3, MM, 64, 64);
    gemm64<2, true, true, 64><<<dim3(64, 8), 256>>>(
        adj, t3, bg2, nullptr, nullptr, nullptr, stat, out2, 512, 4096, 512);

    // gating: za = out1@Wo1^T + bo1; out = sig(za + out2@Wo2^T + bo2)*out1 + (1-sig)*out2
    gemm64<2, false, false, 64><<<dim3(1, MM / 64), 256>>>(
        out1, Wo1, bo1, nullptr, nullptr, nullptr, nullptr, za, MM, 64, 64);
    gemm64<4, false, false, 64><<<dim3(1, MM / 64), 256>>>(
        out2, Wo2, bo2, za, out1, out2, nullptr, out, MM, 64, 64);
}